// round 13
// baseline (speedup 1.0000x reference)
#include <cuda_runtime.h>
#include <cstdint>

// Dykstra alternating projection, n=4096, up to 20 iterations.
//   Xp = X + (1/n + s/n^2) - row_i/n - col_j/n ;  X <- relu(Xp)
//   freeze X once min(Xp) >= 0  (relu(Xp)==Xp in that case)
//
// R12 -> R13: with the atomic floor gone (R12: TMA bulk-reduce for col sums,
// 40.6->24.3us), re-attack the 16 in-loop barriers (2/row from
// blockReduceSum). Per-row warp-shuffle reductions (barrier-free, lane0 ->
// smem) + cvn moved from 16 registers into a 16KB SMEM table keeps regs <=64
// under __launch_bounds__(256,4), preserving 4 blocks/SM / single wave.
// 2 barriers per kernel instead of 18; 8-row load stream pipelines freely.

#define NDIM 4096
#define RPB 8                         // rows per block
#define NBLK (NDIM / RPB)             // 512 blocks
#define NTHREADS 256
#define NWARPS (NTHREADS / 32)        // 8
#define MAXIT 20
#define F4_PER_ROW (NDIM / 4)         // 1024 float4 per row
#define F4_PER_THREAD (F4_PER_ROW / NTHREADS) // 4
#define F4_ZERO_PER_BLK (F4_PER_ROW / NBLK)   // 2
#define COL_BYTES (NDIM * 4)          // 16384 bytes of col partials

__device__ float  g_row[NDIM];              // row sums (exclusive per block)
__device__ float4 g_col[3][F4_PER_ROW];     // col sums, triple-buffered
__device__ float  g_total[MAXIT + 1];       // per-iteration totals
__device__ int    g_neg[MAXIT];             // any-negative flag per iteration

__global__ void init_kernel() {
    int t = threadIdx.x;
    for (int i = t; i < F4_PER_ROW; i += NTHREADS) {
        g_col[0][i] = make_float4(0.f, 0.f, 0.f, 0.f);
        g_col[1][i] = make_float4(0.f, 0.f, 0.f, 0.f);
    }
    if (t <= MAXIT) g_total[t] = 0.f;
    if (t < MAXIT)  g_neg[t] = 0;
}

__device__ __forceinline__ float warpReduceSum(float v) {
    #pragma unroll
    for (int o = 16; o > 0; o >>= 1) v += __shfl_down_sync(0xffffffffu, v, o);
    return v;
}

// One bulk reduce-add of a 16KB SMEM buffer into gmem (async-proxy, sm_90+).
// Caller must have barrier'd after the SMEM writes.
__device__ __forceinline__ void bulk_reduce_add_f32(void* gdst, const void* smem_src) {
    if (threadIdx.x == 0) {
        asm volatile("fence.proxy.async.shared::cta;" ::: "memory");
        uint32_t saddr;
        asm volatile("{\n\t.reg .u64 t;\n\tcvta.to.shared.u64 t, %1;\n\tcvt.u32.u64 %0, t;\n\t}"
                     : "=r"(saddr) : "l"(smem_src));
        asm volatile("{\n\t.reg .u64 g;\n\tcvta.to.global.u64 g, %0;\n\t"
                     "cp.reduce.async.bulk.global.shared::cta.bulk_group.add.f32 [g], [%1], %2;\n\t}"
                     :: "l"((uint64_t)gdst), "r"(saddr), "r"((uint32_t)COL_BYTES) : "memory");
        asm volatile("cp.async.bulk.commit_group;" ::: "memory");
        asm volatile("cp.async.bulk.wait_group 0;" ::: "memory");
    }
}

// Pre-pass: row/col/total sums of the initial X (input for iteration 0).
__global__ __launch_bounds__(NTHREADS, 4)
void reduce0_kernel(const float* __restrict__ X) {
    __shared__ __align__(16) float4 s_colpart[F4_PER_ROW];   // 16KB
    __shared__ float s_part[NWARPS][RPB];
    int t = threadIdx.x;
    int lane = t & 31, wid = t >> 5;
    int row0 = blockIdx.x * RPB;

    float4 cacc[F4_PER_THREAD];
    #pragma unroll
    for (int g = 0; g < F4_PER_THREAD; g++) cacc[g] = make_float4(0.f, 0.f, 0.f, 0.f);

    #pragma unroll
    for (int r = 0; r < RPB; r++) {
        const float4* xr = (const float4*)(X + (size_t)(row0 + r) * NDIM);
        float rp = 0.f;
        #pragma unroll
        for (int g = 0; g < F4_PER_THREAD; g++) {
            float4 v = xr[t + NTHREADS * g];
            rp += (v.x + v.y) + (v.z + v.w);
            cacc[g].x += v.x; cacc[g].y += v.y; cacc[g].z += v.z; cacc[g].w += v.w;
        }
        float rs = warpReduceSum(rp);
        if (lane == 0) s_part[wid][r] = rs;
    }
    #pragma unroll
    for (int g = 0; g < F4_PER_THREAD; g++)
        s_colpart[t + NTHREADS * g] = cacc[g];
    __syncthreads();
    if (t < RPB) {
        float rs = 0.f;
        #pragma unroll
        for (int w = 0; w < NWARPS; w++) rs += s_part[w][t];
        g_row[row0 + t] = rs;
        atomicAdd(&g_total[0], rs);
    }
    bulk_reduce_add_f32(&g_col[0][0], s_colpart);
}

// Iteration k: update X (in place after k=0) + reductions for iteration k+1.
__global__ __launch_bounds__(NTHREADS, 4)
void fused_kernel(const float* __restrict__ Xin, float* __restrict__ Xout,
                  int k, const int* __restrict__ max_iters) {
    __shared__ __align__(16) float4 s_colpart[F4_PER_ROW];   // 16KB (end staging)
    __shared__ __align__(16) float4 s_cvn[F4_PER_ROW];       // 16KB (col/n table)
    __shared__ float s_part[NWARPS][RPB];
    __shared__ float s_rowsub[RPB];
    __shared__ int s_done;
    int t = threadIdx.x;
    int lane = t & 31, wid = t >> 5;
    int row0 = blockIdx.x * RPB;

    const float inv_n = 1.0f / NDIM;
    int rdc = k % 3, wrc = (k + 1) % 3, zc = (k + 2) % 3;

    // Stage pre-scaled col values into SMEM (frees 16 registers) while
    // warp 0 does the done-ballot and warp 1 fetches row subtractors.
    #pragma unroll
    for (int g = 0; g < F4_PER_THREAD; g++) {
        float4 cv = g_col[rdc][t + NTHREADS * g];
        s_cvn[t + NTHREADS * g] =
            make_float4(cv.x * inv_n, cv.y * inv_n, cv.z * inv_n, cv.w * inv_n);
    }
    if (t < 32) {
        int z = (t < k) ? (g_neg[t] == 0) : 0;
        unsigned m = __ballot_sync(0xffffffffu, z);
        if (t == 0) s_done = (m != 0u) || (k >= *max_iters);
    }
    if (t >= 32 && t < 32 + RPB)
        s_rowsub[t - 32] = g_row[row0 + (t - 32)] * inv_n;
    __syncthreads();                                   // barrier #1

    if (s_done) {
        if (k == 0) {  // max_iters==0: output = input (never hit for 20)
            for (int r = 0; r < RPB; r++) {
                const float4* xr = (const float4*)(Xin + (size_t)(row0 + r) * NDIM);
                float4*       yr = (float4*)(Xout + (size_t)(row0 + r) * NDIM);
                #pragma unroll
                for (int g = 0; g < F4_PER_THREAD; g++)
                    yr[t + NTHREADS * g] = xr[t + NTHREADS * g];
            }
        }
        return;
    }

    float total = g_total[k];
    float c = inv_n + total * inv_n * inv_n;

    float4 cacc[F4_PER_THREAD];
    #pragma unroll
    for (int g = 0; g < F4_PER_THREAD; g++) cacc[g] = make_float4(0.f, 0.f, 0.f, 0.f);
    bool neg = false;

    // Hot loop: barrier-free. Row sums via warp shuffles (lane0 -> s_part).
    #pragma unroll
    for (int r = 0; r < RPB; r++) {
        const float4* xr = (const float4*)(Xin + (size_t)(row0 + r) * NDIM);
        float4*       yr = (float4*)(Xout + (size_t)(row0 + r) * NDIM);
        float a = c - s_rowsub[r];
        float rp = 0.f;
        #pragma unroll
        for (int g = 0; g < F4_PER_THREAD; g++) {
            int i = t + NTHREADS * g;
            float4 v = xr[i];
            float4 cvn = s_cvn[i];
            float4 xp;
            xp.x = v.x + a - cvn.x;
            xp.y = v.y + a - cvn.y;
            xp.z = v.z + a - cvn.z;
            xp.w = v.w + a - cvn.w;
            float mn = fminf(fminf(xp.x, xp.y), fminf(xp.z, xp.w));
            neg = neg || (mn < 0.f);
            float4 y;
            y.x = fmaxf(xp.x, 0.f); y.y = fmaxf(xp.y, 0.f);
            y.z = fmaxf(xp.z, 0.f); y.w = fmaxf(xp.w, 0.f);
            yr[i] = y;
            rp += (y.x + y.y) + (y.z + y.w);
            cacc[g].x += y.x; cacc[g].y += y.y; cacc[g].z += y.z; cacc[g].w += y.w;
        }
        float rs = warpReduceSum(rp);
        if (lane == 0) s_part[wid][r] = rs;
    }

    // Stage col partials for the bulk reduce.
    #pragma unroll
    for (int g = 0; g < F4_PER_THREAD; g++)
        s_colpart[t + NTHREADS * g] = cacc[g];

    if (__syncthreads_or(neg ? 1 : 0)) {               // barrier #2
        if (t == 0) g_neg[k] = 1;
    }

    // Row sums + total (rows are block-exclusive: plain stores; 8 tiny atomics).
    if (t < RPB) {
        float rs = 0.f;
        #pragma unroll
        for (int w = 0; w < NWARPS; w++) rs += s_part[w][t];
        g_row[row0 + t] = rs;
        atomicAdd(&g_total[k + 1], rs);
    }

    // Col partials: one TMA-pipe bulk reduce-add (no LSU atomics).
    bulk_reduce_add_f32(&g_col[wrc][0], s_colpart);

    // Zero the col buffer iteration k+1 accumulates into (dead since k-1).
    if (t < F4_ZERO_PER_BLK)
        g_col[zc][blockIdx.x * F4_ZERO_PER_BLK + t] = make_float4(0.f, 0.f, 0.f, 0.f);
}

extern "C" void kernel_launch(void* const* d_in, const int* in_sizes, int n_in,
                              void* d_out, int out_size) {
    const float* X = (const float*)d_in[0];
    const int* max_iters = (const int*)d_in[1];
    float* out = (float*)d_out;
    (void)in_sizes; (void)n_in; (void)out_size;

    init_kernel<<<1, NTHREADS>>>();
    reduce0_kernel<<<NBLK, NTHREADS>>>(X);
    for (int k = 0; k < MAXIT; k++) {
        const float* src = (k == 0) ? X : out;
        fused_kernel<<<NBLK, NTHREADS>>>(src, out, k, max_iters);
    }
}